// round 5
// baseline (speedup 1.0000x reference)
#include <cuda_runtime.h>

// Problem constants (fixed by the dataset)
#define NN 50000
#define EE 800000
#define ET (EE + NN)   // edges + self loops
#define CC 256         // hidden = out channels
#define F1 128         // input features
#define GG 64          // graphs

// ---------------- scratch (device globals; no allocation allowed) ----------
__device__ float g_H[(size_t)NN * CC];     // h = x @ W (reused both layers)
__device__ float g_X2[(size_t)NN * CC];    // layer-1 output / layer-2 input
__device__ float g_gout[GG * CC];          // graph_emb accumulator (device-local)
__device__ float g_asrc[NN];
__device__ float g_adst[NN];
__device__ int   g_off[NN + 1];
__device__ int   g_deg[NN];
__device__ int   g_cur[NN];
__device__ int   g_esrc[ET];

__device__ __forceinline__ int clampN(int v) {
    return v < 0 ? 0 : (v >= NN ? NN - 1 : v);
}

// ---------------- packed fp32x2 FMA (Blackwell; exonerated in R4) -----------
__device__ __forceinline__ float2 ffma2(float2 a, float2 b, float2 c) {
    float2 d;
    asm("fma.rn.f32x2 %0, %1, %2, %3;"
        : "=l"(reinterpret_cast<unsigned long long&>(d))
        : "l"(reinterpret_cast<unsigned long long&>(a)),
          "l"(reinterpret_cast<unsigned long long&>(b)),
          "l"(reinterpret_cast<unsigned long long&>(c)));
    return d;
}

// ---------------- init: deg=1 (self loop), cur=0, zero graph accumulator ----
__global__ void init_kernel() {
    int i = blockIdx.x * blockDim.x + threadIdx.x;
    if (i < NN) { g_deg[i] = 1; g_cur[i] = 0; }
    if (i < GG * CC) g_gout[i] = 0.f;
}

// ---------------- CSR build: count ------------------------------------------
__global__ void count_kernel(const int* __restrict__ ei) {
    int i = blockIdx.x * blockDim.x + threadIdx.x;
    if (i < EE) {
        int d = clampN(ei[EE + i]);   // dst row (edge_index[1])
        atomicAdd(&g_deg[d], 1);
    }
}

// ---------------- CSR build: exclusive scan (single block) ------------------
__global__ void scan_kernel() {
    __shared__ int sums[1024];
    const int t = threadIdx.x;
    const int CH = (NN + 1023) / 1024;   // 49
    int beg = t * CH;
    int end = beg + CH; if (end > NN) end = NN;
    int s = 0;
    for (int i = beg; i < end; i++) s += g_deg[i];
    sums[t] = s;
    __syncthreads();
    for (int d = 1; d < 1024; d <<= 1) {
        int v = 0;
        if (t >= d) v = sums[t - d];
        __syncthreads();
        if (t >= d) sums[t] += v;
        __syncthreads();
    }
    int base = (t == 0) ? 0 : sums[t - 1];
    s = base;
    for (int i = beg; i < end; i++) { s += g_deg[i]; g_off[i + 1] = s; }
    if (t == 0) g_off[0] = 0;
}

// ---------------- CSR build: fill edge sources (incl. self loops) -----------
__global__ void fill_kernel(const int* __restrict__ ei) {
    int i = blockIdx.x * blockDim.x + threadIdx.x;
    if (i < EE) {
        int d = clampN(ei[EE + i]);
        int sv = clampN(ei[i]);
        int p = atomicAdd(&g_cur[d], 1);
        g_esrc[g_off[d] + p] = sv;
    } else if (i < EE + NN) {
        int n = i - EE;
        int p = atomicAdd(&g_cur[n], 1);
        g_esrc[g_off[n] + p] = n;
    }
}

// ---------------- SGEMM: C[M,256] = A[M,K] * B[K,256] into g_H --------------
// 128x128 tile, BK=16, 256 threads, 8x8 micro-tile.
// Register-prefetch double buffering + packed f32x2 FMAs.
__global__ __launch_bounds__(256) void sgemm_kernel(
    const float* __restrict__ Aext, int use_x2,
    const float* __restrict__ B, int M, int K)
{
    const float* A = use_x2 ? g_X2 : Aext;
    float* C = g_H;
    __shared__ float As[16][128];
    __shared__ float Bs[16][128];
    const int bm = blockIdx.x * 128;
    const int bn = blockIdx.y * 128;
    const int tid = threadIdx.x;
    const int tx = tid & 15, ty = tid >> 4;

    float2 acc[8][4];
#pragma unroll
    for (int i = 0; i < 8; i++)
#pragma unroll
        for (int j = 0; j < 4; j++) acc[i][j] = make_float2(0.f, 0.f);

    const int arow0 = tid >> 2;         // 0..63
    const int acol  = (tid & 3) * 4;    // 0,4,8,12
    const int brow  = tid >> 5;         // 0..7
    const int bcol  = (tid & 31) * 4;   // 0..124

    float4 pa[2], pb[2];

    // prefetch tile 0 into registers
#pragma unroll
    for (int r = 0; r < 2; r++) {
        int row = bm + arow0 + r * 64;
        pa[r] = make_float4(0.f, 0.f, 0.f, 0.f);
        if (row < M) pa[r] = *(const float4*)(A + (size_t)row * K + acol);
        pb[r] = *(const float4*)(B + (size_t)(brow + r * 8) * CC + bn + bcol);
    }

    for (int kt = 0; kt < K; kt += 16) {
        // stage current tile to smem
#pragma unroll
        for (int r = 0; r < 2; r++) {
            As[acol + 0][arow0 + r * 64] = pa[r].x;
            As[acol + 1][arow0 + r * 64] = pa[r].y;
            As[acol + 2][arow0 + r * 64] = pa[r].z;
            As[acol + 3][arow0 + r * 64] = pa[r].w;
            *(float4*)&Bs[brow + r * 8][bcol] = pb[r];
        }
        __syncthreads();

        // prefetch next tile into registers (overlaps with compute below)
        if (kt + 16 < K) {
#pragma unroll
            for (int r = 0; r < 2; r++) {
                int row = bm + arow0 + r * 64;
                pa[r] = make_float4(0.f, 0.f, 0.f, 0.f);
                if (row < M) pa[r] = *(const float4*)(A + (size_t)row * K + kt + 16 + acol);
                pb[r] = *(const float4*)(B + (size_t)(kt + 16 + brow + r * 8) * CC + bn + bcol);
            }
        }

#pragma unroll
        for (int kk = 0; kk < 16; kk++) {
            float4 a0 = *(const float4*)&As[kk][ty * 8];
            float4 a1 = *(const float4*)&As[kk][ty * 8 + 4];
            float4 b0 = *(const float4*)&Bs[kk][tx * 8];
            float4 b1 = *(const float4*)&Bs[kk][tx * 8 + 4];
            float av[8] = {a0.x, a0.y, a0.z, a0.w, a1.x, a1.y, a1.z, a1.w};
            float2 bv[4] = {make_float2(b0.x, b0.y), make_float2(b0.z, b0.w),
                            make_float2(b1.x, b1.y), make_float2(b1.z, b1.w)};
#pragma unroll
            for (int i = 0; i < 8; i++) {
                float2 ai = make_float2(av[i], av[i]);
#pragma unroll
                for (int j = 0; j < 4; j++) acc[i][j] = ffma2(ai, bv[j], acc[i][j]);
            }
        }
        __syncthreads();
    }
#pragma unroll
    for (int i = 0; i < 8; i++) {
        int row = bm + ty * 8 + i;
        if (row < M) {
            float* cp = C + (size_t)row * CC + bn + tx * 8;
            *(float4*)cp = make_float4(acc[i][0].x, acc[i][0].y, acc[i][1].x, acc[i][1].y);
            *(float4*)(cp + 4) = make_float4(acc[i][2].x, acc[i][2].y, acc[i][3].x, acc[i][3].y);
        }
    }
}

// ---------------- per-node attention logit projections -----------------------
__global__ void alpha_kernel(const float* __restrict__ aw_s,
                             const float* __restrict__ aw_d) {
    int w = (blockIdx.x * blockDim.x + threadIdx.x) >> 5;
    if (w >= NN) return;
    int lane = threadIdx.x & 31;
    const float4* hr = (const float4*)(g_H + (size_t)w * CC);
    float s = 0.f, d = 0.f;
#pragma unroll
    for (int j = 0; j < 2; j++) {
        float4 h  = hr[lane * 2 + j];
        float4 a  = ((const float4*)aw_s)[lane * 2 + j];
        float4 dd = ((const float4*)aw_d)[lane * 2 + j];
        s += h.x * a.x + h.y * a.y + h.z * a.z + h.w * a.w;
        d += h.x * dd.x + h.y * dd.y + h.z * dd.z + h.w * dd.w;
    }
#pragma unroll
    for (int o = 16; o > 0; o >>= 1) {
        s += __shfl_xor_sync(0xFFFFFFFFu, s, o);
        d += __shfl_xor_sync(0xFFFFFFFFu, d, o);
    }
    if (lane == 0) { g_asrc[w] = s; g_adst[w] = d; }
}

// ---------------- per-dst-node online-softmax aggregation -------------------
// One warp per destination node: lane handles 8 contiguous channels.
template <bool ACT, bool GRAPH>
__global__ void aggregate_kernel(const float* __restrict__ bias,
                                 float* __restrict__ out_ext,
                                 const int* __restrict__ batch) {
    int w = (blockIdx.x * blockDim.x + threadIdx.x) >> 5;
    if (w >= NN) return;
    int lane = threadIdx.x & 31;
    int beg = g_off[w], end = g_off[w + 1];
    float ad = g_adst[w];
    float m = -1e30f, s = 0.f;
    float a0 = 0.f, a1 = 0.f, a2 = 0.f, a3 = 0.f;
    float a4 = 0.f, a5 = 0.f, a6 = 0.f, a7 = 0.f;
    const float4* H4 = (const float4*)g_H;
    for (int i = beg; i < end; i++) {
        int src = g_esrc[i];
        float e = g_asrc[src] + ad;
        e = e > 0.f ? e : 0.2f * e;                 // attention leaky relu
        float mn = fmaxf(m, e);
        float sc = __expf(m - mn);
        float p  = __expf(e - mn);
        s = s * sc + p;
        float4 v0 = H4[(size_t)src * 64 + lane * 2];
        float4 v1 = H4[(size_t)src * 64 + lane * 2 + 1];
        a0 = a0 * sc + p * v0.x;  a1 = a1 * sc + p * v0.y;
        a2 = a2 * sc + p * v0.z;  a3 = a3 * sc + p * v0.w;
        a4 = a4 * sc + p * v1.x;  a5 = a5 * sc + p * v1.y;
        a6 = a6 * sc + p * v1.z;  a7 = a7 * sc + p * v1.w;
        m = mn;
    }
    float inv = 1.f / s;
    int c = lane * 8;
    float o[8];
    o[0] = a0 * inv + bias[c + 0];  o[1] = a1 * inv + bias[c + 1];
    o[2] = a2 * inv + bias[c + 2];  o[3] = a3 * inv + bias[c + 3];
    o[4] = a4 * inv + bias[c + 4];  o[5] = a5 * inv + bias[c + 5];
    o[6] = a6 * inv + bias[c + 6];  o[7] = a7 * inv + bias[c + 7];
    if (ACT) {
#pragma unroll
        for (int j = 0; j < 8; j++) o[j] = o[j] > 0.f ? o[j] : 0.01f * o[j];
    }
    float* out = GRAPH ? out_ext : g_X2;
    float* op = out + (size_t)w * CC + c;
    *(float4*)op       = make_float4(o[0], o[1], o[2], o[3]);
    *(float4*)(op + 4) = make_float4(o[4], o[5], o[6], o[7]);
    if (GRAPH) {
        int g = batch[w];
        g = g < 0 ? 0 : (g >= GG ? GG - 1 : g);
        float* gp = g_gout + g * CC + c;   // device-local accumulator
#pragma unroll
        for (int j = 0; j < 8; j++) atomicAdd(gp + j, o[j]);
    }
}

// ---------------- copy graph accumulator into d_out (plain stores) ----------
__global__ void copy_gout_kernel(float* __restrict__ out) {
    int i = blockIdx.x * blockDim.x + threadIdx.x;
    if (i < GG * CC) out[(size_t)NN * CC + i] = g_gout[i];
}

// ---------------- launch -----------------------------------------------------
extern "C" void kernel_launch(void* const* d_in, const int* in_sizes, int n_in,
                              void* d_out, int out_size) {
    const float* x     = (const float*)d_in[0];
    const int*   ei    = (const int*)d_in[1];     // edge_index: int32 (JAX x64 off)
    const int*   batch = (const int*)d_in[2];     // batch: int32
    const float* W1    = (const float*)d_in[3];
    const float* as1   = (const float*)d_in[4];
    const float* ad1   = (const float*)d_in[5];
    const float* b1    = (const float*)d_in[6];
    const float* W2    = (const float*)d_in[7];
    const float* as2   = (const float*)d_in[8];
    const float* ad2   = (const float*)d_in[9];
    const float* b2    = (const float*)d_in[10];

    float* out = (float*)d_out;

    const int T = 256;
    // CSR build (dst is identical for both layers; built once per launch)
    init_kernel<<<(NN + T - 1) / T, T>>>();
    count_kernel<<<(EE + T - 1) / T, T>>>(ei);
    scan_kernel<<<1, 1024>>>();
    fill_kernel<<<(EE + NN + T - 1) / T, T>>>(ei);

    dim3 ggrid((NN + 127) / 128, CC / 128);
    const int WGRID = (NN * 32 + T - 1) / T;

    // Layer 1
    sgemm_kernel<<<ggrid, T>>>(x, 0, W1, NN, F1);
    alpha_kernel<<<WGRID, T>>>(as1, ad1);
    aggregate_kernel<true, false><<<WGRID, T>>>(b1, nullptr, nullptr);

    // Layer 2
    sgemm_kernel<<<ggrid, T>>>(nullptr, 1, W2, NN, CC);
    alpha_kernel<<<WGRID, T>>>(as2, ad2);
    aggregate_kernel<false, true><<<WGRID, T>>>(b2, out, batch);

    copy_gout_kernel<<<(GG * CC + T - 1) / T, T>>>(out);
}

// round 6
// speedup vs baseline: 1.2869x; 1.2869x over previous
#include <cuda_runtime.h>
#include <cuda_bf16.h>

// Problem constants (fixed by the dataset)
#define NN 50000
#define EE 800000
#define ET (EE + NN)   // edges + self loops
#define CC 256         // hidden = out channels
#define F1 128         // input features
#define GG 64          // graphs

// ---------------- scratch (device globals; no allocation allowed) ----------
__device__ float g_H[(size_t)NN * CC];     // h = x @ W (reused both layers)
__device__ float g_X2[(size_t)NN * CC];    // layer-1 output / layer-2 input
__device__ float g_gout[GG * CC];          // graph_emb accumulator (device-local)
__device__ float g_asrc[NN];
__device__ float g_adst[NN];
__device__ int   g_off[NN + 1];
__device__ int   g_deg[NN];
__device__ int   g_cur[NN];
__device__ int   g_esrc[ET];

__device__ __forceinline__ int clampN(int v) {
    return v < 0 ? 0 : (v >= NN ? NN - 1 : v);
}

// ---------------- init: deg=1 (self loop), cur=0, zero graph accumulator ----
__global__ void init_kernel() {
    int i = blockIdx.x * blockDim.x + threadIdx.x;
    if (i < NN) { g_deg[i] = 1; g_cur[i] = 0; }
    if (i < GG * CC) g_gout[i] = 0.f;
}

// ---------------- CSR build: count ------------------------------------------
__global__ void count_kernel(const int* __restrict__ ei) {
    int i = blockIdx.x * blockDim.x + threadIdx.x;
    if (i < EE) {
        int d = clampN(ei[EE + i]);   // dst row (edge_index[1])
        atomicAdd(&g_deg[d], 1);
    }
}

// ---------------- CSR build: exclusive scan (single block) ------------------
__global__ void scan_kernel() {
    __shared__ int sums[1024];
    const int t = threadIdx.x;
    const int CH = (NN + 1023) / 1024;   // 49
    int beg = t * CH;
    int end = beg + CH; if (end > NN) end = NN;
    int s = 0;
    for (int i = beg; i < end; i++) s += g_deg[i];
    sums[t] = s;
    __syncthreads();
    for (int d = 1; d < 1024; d <<= 1) {
        int v = 0;
        if (t >= d) v = sums[t - d];
        __syncthreads();
        if (t >= d) sums[t] += v;
        __syncthreads();
    }
    int base = (t == 0) ? 0 : sums[t - 1];
    s = base;
    for (int i = beg; i < end; i++) { s += g_deg[i]; g_off[i + 1] = s; }
    if (t == 0) g_off[0] = 0;
}

// ---------------- CSR build: fill edge sources (incl. self loops) -----------
__global__ void fill_kernel(const int* __restrict__ ei) {
    int i = blockIdx.x * blockDim.x + threadIdx.x;
    if (i < EE) {
        int d = clampN(ei[EE + i]);
        int sv = clampN(ei[i]);
        int p = atomicAdd(&g_cur[d], 1);
        g_esrc[g_off[d] + p] = sv;
    } else if (i < EE + NN) {
        int n = i - EE;
        int p = atomicAdd(&g_cur[n], 1);
        g_esrc[g_off[n] + p] = n;
    }
}

// ================= bf16 split-precision tensor-core GEMM ====================
// C[M,256] = A[M,K] * B[K,256] in ~fp32 precision:
//   A = Ah + Al (bf16 each), B = Bh + Bl;  C += Ah*Bh + Ah*Bl + Al*Bh
// CTA tile 128x128x32, 8 warps of 64x32, mma.sync.m16n8k16.bf16.

__device__ __forceinline__ unsigned pk(__nv_bfloat16 a, __nv_bfloat16 b) {
    return (unsigned)__bfloat16_as_ushort(a) |
           ((unsigned)__bfloat16_as_ushort(b) << 16);
}

__device__ __forceinline__ void ldsm_x4(unsigned& r0, unsigned& r1,
                                        unsigned& r2, unsigned& r3,
                                        unsigned addr) {
    asm volatile("ldmatrix.sync.aligned.m8n8.x4.shared.b16 {%0,%1,%2,%3}, [%4];"
                 : "=r"(r0), "=r"(r1), "=r"(r2), "=r"(r3) : "r"(addr));
}
__device__ __forceinline__ void ldsm_x2t(unsigned& r0, unsigned& r1,
                                         unsigned addr) {
    asm volatile("ldmatrix.sync.aligned.m8n8.x2.trans.shared.b16 {%0,%1}, [%2];"
                 : "=r"(r0), "=r"(r1) : "r"(addr));
}
__device__ __forceinline__ void mma_bf16(float* c, const unsigned* a,
                                         const unsigned* b) {
    asm volatile(
        "mma.sync.aligned.m16n8k16.row.col.f32.bf16.bf16.f32 "
        "{%0,%1,%2,%3}, {%4,%5,%6,%7}, {%8,%9}, {%0,%1,%2,%3};"
        : "+f"(c[0]), "+f"(c[1]), "+f"(c[2]), "+f"(c[3])
        : "r"(a[0]), "r"(a[1]), "r"(a[2]), "r"(a[3]), "r"(b[0]), "r"(b[1]));
}

#define APITCH 40   // bf16 elems per A smem row (32 + 8 pad) -> conflict-free
#define BPITCH 136  // bf16 elems per B smem row (128 + 8 pad)

__global__ __launch_bounds__(256) void mma_gemm_kernel(
    const float* __restrict__ Aext, int use_x2,
    const float* __restrict__ B, int M, int K)
{
    const float* A = use_x2 ? g_X2 : Aext;
    float* C = g_H;

    __shared__ __align__(16) __nv_bfloat16 sAh[128][APITCH];
    __shared__ __align__(16) __nv_bfloat16 sAl[128][APITCH];
    __shared__ __align__(16) __nv_bfloat16 sBh[32][BPITCH];
    __shared__ __align__(16) __nv_bfloat16 sBl[32][BPITCH];

    const int tid  = threadIdx.x;
    const int lane = tid & 31;
    const int wid  = tid >> 5;
    const int wm   = wid & 1;    // 0,1 -> m half (64)
    const int wn   = wid >> 1;   // 0..3 -> n quarter (32)
    const int bm   = blockIdx.x * 128;
    const int bn   = blockIdx.y * 128;

    // ldmatrix lane-address components
    const int a_m_off = (lane & 7) + ((lane >> 3) & 1) * 8;  // within m16
    const int a_k_off = (lane >> 4) * 8;                     // within k16
    const int b_k_in  = lane & 15;                           // within k16

    const unsigned sAh0 = (unsigned)__cvta_generic_to_shared(&sAh[0][0]);
    const unsigned sAl0 = (unsigned)__cvta_generic_to_shared(&sAl[0][0]);
    const unsigned sBh0 = (unsigned)__cvta_generic_to_shared(&sBh[0][0]);
    const unsigned sBl0 = (unsigned)__cvta_generic_to_shared(&sBl[0][0]);

    float cacc[4][4][4];
#pragma unroll
    for (int i = 0; i < 4; i++)
#pragma unroll
        for (int j = 0; j < 4; j++)
#pragma unroll
            for (int r = 0; r < 4; r++) cacc[i][j][r] = 0.f;

    for (int kt = 0; kt < K; kt += 32) {
        // ---- stage A tile (128 x 32 fp32) as hi/lo bf16 ----
#pragma unroll
        for (int i = 0; i < 4; i++) {
            int idx = tid + i * 256;           // 0..1023
            int row = idx >> 3;                // 0..127
            int c   = (idx & 7) * 4;           // 0..28
            int grow = bm + row;
            float4 v = make_float4(0.f, 0.f, 0.f, 0.f);
            if (grow < M) v = *(const float4*)(A + (size_t)grow * K + kt + c);
            __nv_bfloat16 h0 = __float2bfloat16(v.x);
            __nv_bfloat16 h1 = __float2bfloat16(v.y);
            __nv_bfloat16 h2 = __float2bfloat16(v.z);
            __nv_bfloat16 h3 = __float2bfloat16(v.w);
            __nv_bfloat16 l0 = __float2bfloat16(v.x - __bfloat162float(h0));
            __nv_bfloat16 l1 = __float2bfloat16(v.y - __bfloat162float(h1));
            __nv_bfloat16 l2 = __float2bfloat16(v.z - __bfloat162float(h2));
            __nv_bfloat16 l3 = __float2bfloat16(v.w - __bfloat162float(h3));
            *(uint2*)&sAh[row][c] = make_uint2(pk(h0, h1), pk(h2, h3));
            *(uint2*)&sAl[row][c] = make_uint2(pk(l0, l1), pk(l2, l3));
        }
        // ---- stage B tile (32 x 128 fp32) as hi/lo bf16 ----
#pragma unroll
        for (int i = 0; i < 4; i++) {
            int idx = tid + i * 256;           // 0..1023
            int krow = idx >> 5;               // 0..31
            int c    = (idx & 31) * 4;         // 0..124
            float4 v = *(const float4*)(B + (size_t)(kt + krow) * CC + bn + c);
            __nv_bfloat16 h0 = __float2bfloat16(v.x);
            __nv_bfloat16 h1 = __float2bfloat16(v.y);
            __nv_bfloat16 h2 = __float2bfloat16(v.z);
            __nv_bfloat16 h3 = __float2bfloat16(v.w);
            __nv_bfloat16 l0 = __float2bfloat16(v.x - __bfloat162float(h0));
            __nv_bfloat16 l1 = __float2bfloat16(v.y - __bfloat162float(h1));
            __nv_bfloat16 l2 = __float2bfloat16(v.z - __bfloat162float(h2));
            __nv_bfloat16 l3 = __float2bfloat16(v.w - __bfloat162float(h3));
            *(uint2*)&sBh[krow][c] = make_uint2(pk(h0, h1), pk(h2, h3));
            *(uint2*)&sBl[krow][c] = make_uint2(pk(l0, l1), pk(l2, l3));
        }
        __syncthreads();

        // ---- compute: 2 k16 halves ----
#pragma unroll
        for (int half = 0; half < 2; half++) {
            const int kk = half * 16;
            unsigned ah[4][4], al[4][4], bh[4][2], bl[4][2];
#pragma unroll
            for (int mi = 0; mi < 4; mi++) {
                int m = wm * 64 + mi * 16 + a_m_off;
                unsigned off = (unsigned)(m * APITCH + kk + a_k_off) * 2u;
                ldsm_x4(ah[mi][0], ah[mi][1], ah[mi][2], ah[mi][3], sAh0 + off);
                ldsm_x4(al[mi][0], al[mi][1], al[mi][2], al[mi][3], sAl0 + off);
            }
#pragma unroll
            for (int nj = 0; nj < 4; nj++) {
                int n = wn * 32 + nj * 8;
                unsigned off = (unsigned)((kk + b_k_in) * BPITCH + n) * 2u;
                ldsm_x2t(bh[nj][0], bh[nj][1], sBh0 + off);
                ldsm_x2t(bl[nj][0], bl[nj][1], sBl0 + off);
            }
#pragma unroll
            for (int mi = 0; mi < 4; mi++)
#pragma unroll
                for (int nj = 0; nj < 4; nj++) {
                    mma_bf16(cacc[mi][nj], ah[mi], bh[nj]);
                    mma_bf16(cacc[mi][nj], ah[mi], bl[nj]);
                    mma_bf16(cacc[mi][nj], al[mi], bh[nj]);
                }
        }
        __syncthreads();
    }

    // ---- epilogue: write C (fp32) ----
    const int grp = lane >> 2;          // 0..7 row within m8
    const int qp  = (lane & 3) * 2;     // col pair
#pragma unroll
    for (int mi = 0; mi < 4; mi++) {
        int r0 = bm + wm * 64 + mi * 16 + grp;
#pragma unroll
        for (int nj = 0; nj < 4; nj++) {
            int col = bn + wn * 32 + nj * 8 + qp;
            float* base = C + (size_t)r0 * CC + col;
            if (r0 < M)
                *(float2*)base = make_float2(cacc[mi][nj][0], cacc[mi][nj][1]);
            if (r0 + 8 < M)
                *(float2*)(base + 8 * CC) =
                    make_float2(cacc[mi][nj][2], cacc[mi][nj][3]);
        }
    }
}

// ---------------- per-node attention logit projections -----------------------
__global__ void alpha_kernel(const float* __restrict__ aw_s,
                             const float* __restrict__ aw_d) {
    int w = (blockIdx.x * blockDim.x + threadIdx.x) >> 5;
    if (w >= NN) return;
    int lane = threadIdx.x & 31;
    const float4* hr = (const float4*)(g_H + (size_t)w * CC);
    float s = 0.f, d = 0.f;
#pragma unroll
    for (int j = 0; j < 2; j++) {
        float4 h  = hr[lane * 2 + j];
        float4 a  = ((const float4*)aw_s)[lane * 2 + j];
        float4 dd = ((const float4*)aw_d)[lane * 2 + j];
        s += h.x * a.x + h.y * a.y + h.z * a.z + h.w * a.w;
        d += h.x * dd.x + h.y * dd.y + h.z * dd.z + h.w * dd.w;
    }
#pragma unroll
    for (int o = 16; o > 0; o >>= 1) {
        s += __shfl_xor_sync(0xFFFFFFFFu, s, o);
        d += __shfl_xor_sync(0xFFFFFFFFu, d, o);
    }
    if (lane == 0) { g_asrc[w] = s; g_adst[w] = d; }
}

// ---------------- per-dst-node online-softmax aggregation -------------------
template <bool ACT, bool GRAPH>
__global__ void aggregate_kernel(const float* __restrict__ bias,
                                 float* __restrict__ out_ext,
                                 const int* __restrict__ batch) {
    int w = (blockIdx.x * blockDim.x + threadIdx.x) >> 5;
    if (w >= NN) return;
    int lane = threadIdx.x & 31;
    int beg = g_off[w], end = g_off[w + 1];
    float ad = g_adst[w];
    float m = -1e30f, s = 0.f;
    float a0 = 0.f, a1 = 0.f, a2 = 0.f, a3 = 0.f;
    float a4 = 0.f, a5 = 0.f, a6 = 0.f, a7 = 0.f;
    const float4* H4 = (const float4*)g_H;
    for (int i = beg; i < end; i++) {
        int src = g_esrc[i];
        float e = g_asrc[src] + ad;
        e = e > 0.f ? e : 0.2f * e;                 // attention leaky relu
        float mn = fmaxf(m, e);
        float sc = __expf(m - mn);
        float p  = __expf(e - mn);
        s = s * sc + p;
        float4 v0 = H4[(size_t)src * 64 + lane * 2];
        float4 v1 = H4[(size_t)src * 64 + lane * 2 + 1];
        a0 = a0 * sc + p * v0.x;  a1 = a1 * sc + p * v0.y;
        a2 = a2 * sc + p * v0.z;  a3 = a3 * sc + p * v0.w;
        a4 = a4 * sc + p * v1.x;  a5 = a5 * sc + p * v1.y;
        a6 = a6 * sc + p * v1.z;  a7 = a7 * sc + p * v1.w;
        m = mn;
    }
    float inv = 1.f / s;
    int c = lane * 8;
    float o[8];
    o[0] = a0 * inv + bias[c + 0];  o[1] = a1 * inv + bias[c + 1];
    o[2] = a2 * inv + bias[c + 2];  o[3] = a3 * inv + bias[c + 3];
    o[4] = a4 * inv + bias[c + 4];  o[5] = a5 * inv + bias[c + 5];
    o[6] = a6 * inv + bias[c + 6];  o[7] = a7 * inv + bias[c + 7];
    if (ACT) {
#pragma unroll
        for (int j = 0; j < 8; j++) o[j] = o[j] > 0.f ? o[j] : 0.01f * o[j];
    }
    float* out = GRAPH ? out_ext : g_X2;
    float* op = out + (size_t)w * CC + c;
    *(float4*)op       = make_float4(o[0], o[1], o[2], o[3]);
    *(float4*)(op + 4) = make_float4(o[4], o[5], o[6], o[7]);
    if (GRAPH) {
        int g = batch[w];
        g = g < 0 ? 0 : (g >= GG ? GG - 1 : g);
        float* gp = g_gout + g * CC + c;   // device-local accumulator
#pragma unroll
        for (int j = 0; j < 8; j++) atomicAdd(gp + j, o[j]);
    }
}

// ---------------- copy graph accumulator into d_out (plain stores) ----------
__global__ void copy_gout_kernel(float* __restrict__ out) {
    int i = blockIdx.x * blockDim.x + threadIdx.x;
    if (i < GG * CC) out[(size_t)NN * CC + i] = g_gout[i];
}

// ---------------- launch -----------------------------------------------------
extern "C" void kernel_launch(void* const* d_in, const int* in_sizes, int n_in,
                              void* d_out, int out_size) {
    const float* x     = (const float*)d_in[0];
    const int*   ei    = (const int*)d_in[1];     // edge_index: int32 (JAX x64 off)
    const int*   batch = (const int*)d_in[2];     // batch: int32
    const float* W1    = (const float*)d_in[3];
    const float* as1   = (const float*)d_in[4];
    const float* ad1   = (const float*)d_in[5];
    const float* b1    = (const float*)d_in[6];
    const float* W2    = (const float*)d_in[7];
    const float* as2   = (const float*)d_in[8];
    const float* ad2   = (const float*)d_in[9];
    const float* b2    = (const float*)d_in[10];

    float* out = (float*)d_out;

    const int T = 256;
    // CSR build (dst is identical for both layers; built once per launch)
    init_kernel<<<(NN + T - 1) / T, T>>>();
    count_kernel<<<(EE + T - 1) / T, T>>>(ei);
    scan_kernel<<<1, 1024>>>();
    fill_kernel<<<(EE + NN + T - 1) / T, T>>>(ei);

    dim3 ggrid((NN + 127) / 128, CC / 128);
    const int WGRID = (NN * 32 + T - 1) / T;

    // Layer 1
    mma_gemm_kernel<<<ggrid, T>>>(x, 0, W1, NN, F1);
    alpha_kernel<<<WGRID, T>>>(as1, ad1);
    aggregate_kernel<true, false><<<WGRID, T>>>(b1, nullptr, nullptr);

    // Layer 2
    mma_gemm_kernel<<<ggrid, T>>>(nullptr, 1, W2, NN, CC);
    alpha_kernel<<<WGRID, T>>>(as2, ad2);
    aggregate_kernel<false, true><<<WGRID, T>>>(b2, out, batch);

    copy_gout_kernel<<<(GG * CC + T - 1) / T, T>>>(out);
}